// round 9
// baseline (speedup 1.0000x reference)
#include <cuda_runtime.h>
#include <cuda_fp16.h>
#include <math.h>
#include <stdint.h>

// ---------------------------------------------------------------------------
// FPLSTM: S=512, B=128, I=H=1024.
//   pre = X @ Wx^T + bx            (SIMT fp16 mma, cp.async 3-stage, 512 thr)
//   recurrence: persistent, 128 CTAs in 2 independent groups of 64.
//   Group g owns batch rows [64g,64g+64); CTA j owns 16 h-columns.
//   fp16 weights SMEM-resident; h/m tiles streamed via 4-buffer cp.async.
//   512 threads/CTA (4 warps/SMSP) + ldmatrix fragment loads.
// ---------------------------------------------------------------------------

namespace {
constexpr int SEQ  = 512;
constexpr int NB   = 128;
constexpr int K    = 1024;
constexpr int H    = 1024;
constexpr int NPRE = 5 * H;

constexpr int GCTA  = 64;
constexpr int GROWS = 64;
constexpr int UCOLS = 16;
constexpr int LDWW  = K / 2 + 4;     // weight row stride (u32 words) = 516
constexpr int BK    = 64;            // K-tile in halves
constexpr int NKT   = K / BK;        // 16
constexpr int LDA   = 36;            // A row stride words (32 data + 4 pad)
constexpr int ABUF  = GROWS * LDA;   // 2304 words / stage
constexpr int IOFP  = 17;
constexpr int IOFSZ = GROWS * IOFP;

constexpr int OFF_W   = 0;                      // 80 rows x LDWW
constexpr int OFF_AS  = 80 * LDWW;              // 41280
constexpr int OFF_IOF = OFF_AS + 4 * ABUF;      // 50496
constexpr int OFF_C   = OFF_IOF + 3 * IOFSZ;    // 53760
constexpr int SMEM_WORDS = OFF_C + IOFSZ;       // 54848 -> 219392 B

constexpr int LDA_P  = 36;
constexpr int P_STAGE = 256 * LDA_P;            // 9216 words
constexpr int P_SMEM  = 3 * P_STAGE;            // 110592 B
constexpr int BKP    = 64;
constexpr int NKT_P  = 16;
constexpr size_t X4 = (size_t)SEQ * NB * K / 4;
constexpr size_t W4 = (size_t)NPRE * K / 4;
}

__device__ __align__(16) float  g_pre[(size_t)SEQ * NB * NPRE];
__device__ __align__(16) __half g_xh[(size_t)SEQ * NB * K];
__device__ __align__(16) __half g_wxh[(size_t)NPRE * K];
__device__ __align__(16) __half g_hh[NB * H];
__device__ __align__(16) __half g_mh[NB * H];
__device__ unsigned g_bars[2];

__device__ __forceinline__ uint32_t pack_h2(float x, float y) {
    __half2 h = __floats2half2_rn(x, y);
    return *reinterpret_cast<uint32_t*>(&h);
}
__device__ __forceinline__ float fast_sigmoid(float x) {
    return __fdividef(1.0f, 1.0f + __expf(-x));
}
__device__ __forceinline__ float fast_tanh(float x) {
    return 1.0f - __fdividef(2.0f, __expf(2.0f * x) + 1.0f);
}
__device__ __forceinline__ void cp16(uint32_t saddr, const void* g) {
    asm volatile("cp.async.cg.shared.global [%0], [%1], 16;\n" :: "r"(saddr), "l"(g));
}
__device__ __forceinline__ void cp_commit() { asm volatile("cp.async.commit_group;\n"); }
template <int N> __device__ __forceinline__ void cp_wait() {
    asm volatile("cp.async.wait_group %0;\n" :: "n"(N));
}
__device__ __forceinline__ void mma_f16(float* c, const uint32_t* a, const uint32_t* b) {
    asm volatile(
        "mma.sync.aligned.m16n8k16.row.col.f32.f16.f16.f32 "
        "{%0,%1,%2,%3}, {%4,%5,%6,%7}, {%8,%9}, {%0,%1,%2,%3};\n"
        : "+f"(c[0]), "+f"(c[1]), "+f"(c[2]), "+f"(c[3])
        : "r"(a[0]), "r"(a[1]), "r"(a[2]), "r"(a[3]), "r"(b[0]), "r"(b[1]));
}
__device__ __forceinline__ void ldsm_x4(uint32_t* r, uint32_t saddr) {
    asm volatile("ldmatrix.sync.aligned.m8n8.x4.shared.b16 {%0,%1,%2,%3}, [%4];"
                 : "=r"(r[0]), "=r"(r[1]), "=r"(r[2]), "=r"(r[3]) : "r"(saddr));
}

// ---------------------------------------------------------------------------
// round_kernel: fp16-convert X and Wx; reset group barriers
// ---------------------------------------------------------------------------
__global__ __launch_bounds__(256) void round_kernel(const float4* __restrict__ X,
                                                    const float4* __restrict__ Wx) {
    const size_t i = (size_t)blockIdx.x * 256 + threadIdx.x;
    if (i < 2) g_bars[i] = 0u;
    if (i < X4) {
        const float4 v = X[i];
        reinterpret_cast<uint2*>(g_xh)[i] = make_uint2(pack_h2(v.x, v.y), pack_h2(v.z, v.w));
    } else if (i < X4 + W4) {
        const size_t j = i - X4;
        const float4 v = Wx[j];
        reinterpret_cast<uint2*>(g_wxh)[j] = make_uint2(pack_h2(v.x, v.y), pack_h2(v.z, v.w));
    }
}

// ---------------------------------------------------------------------------
// pre_kernel: pre = Xh @ Wxh^T + bx  (BM=128, BN=128, BK=64, 512 threads)
// ---------------------------------------------------------------------------
__device__ __forceinline__ void pre_issue(uint32_t smbase, int stage,
                                          const __half* __restrict__ Asrc,
                                          const __half* __restrict__ Bsrc,
                                          int kt, int tid) {
    const uint32_t sb = smbase + (uint32_t)(stage * P_STAGE) * 4u;
    #pragma unroll
    for (int j = 0; j < 4; ++j) {
        const int i  = tid + j * 512;
        const int r  = i >> 3;
        const int ch = i & 7;
        const __half* src = (r < 128)
            ? Asrc + (size_t)r * K + kt + ch * 8
            : Bsrc + (size_t)(r - 128) * K + kt + ch * 8;
        cp16(sb + (uint32_t)(r * LDA_P + ch * 4) * 4u, src);
    }
    cp_commit();
}

__global__ __launch_bounds__(512, 1) void pre_kernel(const float* __restrict__ bx) {
    extern __shared__ uint32_t sm_u[];
    const uint32_t smbase = (uint32_t)__cvta_generic_to_shared(sm_u);
    const int tid  = threadIdx.x;
    const int lane = tid & 31;
    const int warp = tid >> 5;
    const int wm = warp >> 2;        // 0..3 : 32 rows each
    const int wn = warp & 3;         // 0..3 : 32 cols each
    const int ar = lane >> 2;
    const int aq = lane & 3;

    // ldmatrix lane offsets (bytes within a stage)
    uint32_t aoff[2], boff[2];
    #pragma unroll
    for (int mt = 0; mt < 2; ++mt)
        aoff[mt] = (uint32_t)((wm * 32 + mt * 16 + (lane & 15)) * LDA_P) * 4u
                 + (uint32_t)((lane >> 4) * 16);
    #pragma unroll
    for (int tp = 0; tp < 2; ++tp)
        boff[tp] = (uint32_t)((128 + wn * 32 + tp * 16 + (lane & 7)
                               + ((lane & 16) ? 8 : 0)) * LDA_P) * 4u
                 + (uint32_t)((lane & 8) ? 16 : 0);

    const __half* Asrc = g_xh  + (size_t)blockIdx.y * 128 * K;
    const __half* Bsrc = g_wxh + (size_t)blockIdx.x * 128 * K;
    float acc[2][4][4] = {};

    pre_issue(smbase, 0, Asrc, Bsrc, 0, tid);
    pre_issue(smbase, 1, Asrc, Bsrc, BKP, tid);

    #pragma unroll 1
    for (int kt = 0; kt < NKT_P; ++kt) {
        if (kt < NKT_P - 2) { cp_wait<1>(); } else { cp_wait<0>(); }
        __syncthreads();
        if (kt + 2 < NKT_P)
            pre_issue(smbase, (kt + 2) % 3, Asrc, Bsrc, (kt + 2) * BKP, tid);

        const uint32_t sb = smbase + (uint32_t)((kt % 3) * P_STAGE) * 4u;
        #pragma unroll
        for (int g = 0; g < 4; ++g) {
            uint32_t af[2][4], bf[2][4];
            #pragma unroll
            for (int mt = 0; mt < 2; ++mt) ldsm_x4(af[mt], sb + aoff[mt] + g * 32);
            #pragma unroll
            for (int tp = 0; tp < 2; ++tp) ldsm_x4(bf[tp], sb + boff[tp] + g * 32);
            #pragma unroll
            for (int mt = 0; mt < 2; ++mt) {
                mma_f16(&acc[mt][0][0], af[mt], &bf[0][0]);
                mma_f16(&acc[mt][1][0], af[mt], &bf[0][2]);
                mma_f16(&acc[mt][2][0], af[mt], &bf[1][0]);
                mma_f16(&acc[mt][3][0], af[mt], &bf[1][2]);
            }
        }
    }

    #pragma unroll
    for (int mt = 0; mt < 2; ++mt)
        #pragma unroll
        for (int tn = 0; tn < 4; ++tn) {
            const int r0 = wm * 32 + mt * 16 + ar;
            const int c0 = wn * 32 + tn * 8 + aq * 2;
            #pragma unroll
            for (int j = 0; j < 4; ++j) {
                const int rr = r0 + (j >> 1) * 8;
                const int cc = c0 + (j & 1);
                const int gm = blockIdx.y * 128 + rr;
                const int gn = blockIdx.x * 128 + cc;
                g_pre[(size_t)gm * NPRE + gn] = acc[mt][tn][j] + __ldg(bx + gn);
            }
        }
}

// ---------------------------------------------------------------------------
// Persistent recurrence kernel, 2 groups x 64 CTAs, 512 threads
// ---------------------------------------------------------------------------
__device__ __forceinline__ void group_barrier(unsigned* bar, unsigned target) {
    __syncthreads();
    if (threadIdx.x == 0) {
        asm volatile("red.release.gpu.global.add.u32 [%0], %1;\n"
                     :: "l"(bar), "r"(1u) : "memory");
        unsigned v;
        do {
            asm volatile("ld.acquire.gpu.global.u32 %0, [%1];\n"
                         : "=r"(v) : "l"(bar) : "memory");
        } while (v < target);
    }
    __syncthreads();
}

// copy one 64 x 64-half A-tile (8KB): exactly 1 cp16 per thread
__device__ __forceinline__ void lstm_issueA(uint32_t smbase, int stage,
                                            const __half* __restrict__ src,
                                            int kt, int tid) {
    const uint32_t sb = smbase + (uint32_t)(OFF_AS + stage * ABUF) * 4u;
    const int r  = tid >> 3;
    const int ch = tid & 7;
    cp16(sb + (uint32_t)(r * LDA + ch * 4) * 4u,
         src + (size_t)r * H + kt + ch * 8);
    cp_commit();
}

__global__ __launch_bounds__(512, 1) void lstm_kernel(const float* __restrict__ Wh,
                                                      const float* __restrict__ bh,
                                                      const float* __restrict__ Wum,
                                                      const float* __restrict__ bum,
                                                      float* __restrict__ out) {
    extern __shared__ uint32_t sm_u[];
    const uint32_t smbase = (uint32_t)__cvta_generic_to_shared(sm_u);
    uint32_t* W_s  = sm_u + OFF_W;
    float*    iof  = reinterpret_cast<float*>(sm_u + OFF_IOF);
    float*    c_s  = reinterpret_cast<float*>(sm_u + OFF_C);

    const int tid   = threadIdx.x;
    const int lane  = tid & 31;
    const int warp  = tid >> 5;
    const int cta   = blockIdx.x;
    const int grp   = cta >> 6;
    const int jj    = cta & 63;
    const int uBase = jj * UCOLS;
    const int gRow0 = grp * GROWS;
    unsigned* bar   = &g_bars[grp];

    // weights: rows 0..63 = Wh[(n>>4)*H + uBase + (n&15)], 64..79 = Wum[uBase+r]
    for (int i = tid; i < 80 * 512; i += 512) {
        const int row = i >> 9;
        const int w   = i & 511;
        const float* src = (row < 64)
            ? Wh  + (size_t)((row >> 4) * H + uBase + (row & 15)) * K
            : Wum + (size_t)(uBase + (row - 64)) * K;
        const float2 v = *reinterpret_cast<const float2*>(src + w * 2);
        W_s[row * LDWW + w] = pack_h2(v.x, v.y);
    }
    for (int i = tid; i < IOFSZ; i += 512) c_s[i] = 0.0f;
    __syncthreads();

    const int ar = lane >> 2;
    const int aq = lane & 3;

    // phase-1 warp layout: wm (0..3) -> 16 batch rows; wn (0..3) == gate index
    const int wm = warp >> 2;
    const int wn = warp & 3;
    const uint32_t aoff1 = (uint32_t)((wm * 16 + (lane & 15)) * LDA) * 4u
                         + (uint32_t)((lane >> 4) * 16);
    const uint32_t boff1 = (uint32_t)((wn * 16 + (lane & 7)
                               + ((lane & 16) ? 8 : 0)) * LDWW) * 4u
                         + (uint32_t)((lane & 8) ? 16 : 0);

    // phase-2 warp layout (warps 0-7): wm2 (0..3) rows, wn2 (0..1) 8 cols
    const int wm2 = warp >> 1;
    const int wn2 = warp & 1;
    const uint32_t aoff2 = (uint32_t)((wm2 * 16 + (lane & 15)) * LDA) * 4u
                         + (uint32_t)((lane >> 4) * 16);
    const uint32_t boff2 = (uint32_t)((64 + wn2 * 8 + (lane & 7)) * LDWW) * 4u
                         + (uint32_t)((lane >> 3) * 16);

    float bhreg[2][2];
    #pragma unroll
    for (int tn = 0; tn < 2; ++tn)
        #pragma unroll
        for (int jb = 0; jb < 2; ++jb)
            bhreg[tn][jb] = bh[wn * H + uBase + tn * 8 + aq * 2 + jb];
    float bureg[2] = {0.0f, 0.0f};
    if (warp < 8) {
        bureg[0] = bum[uBase + wn2 * 8 + aq * 2];
        bureg[1] = bum[uBase + wn2 * 8 + aq * 2 + 1];
    }

    unsigned tgt = GCTA;

    #pragma unroll 1
    for (int t = 0; t < SEQ; ++t) {
        const float* pre_t = g_pre + (size_t)t * NB * NPRE;

        // ================= Phase 1: gates =================
        {
            float2 pre2[2][2];   // [tn][jh]
            #pragma unroll
            for (int tn = 0; tn < 2; ++tn)
                #pragma unroll
                for (int jh = 0; jh < 2; ++jh) {
                    const int b = wm * 16 + ar + 8 * jh;
                    pre2[tn][jh] = __ldcg(reinterpret_cast<const float2*>(
                        pre_t + (size_t)(gRow0 + b) * NPRE + wn * H + uBase + tn * 8 + aq * 2));
                }

            float acc[2][4] = {};
            if (t > 0) {
                const __half* hsrc = g_hh + (size_t)gRow0 * H;
                lstm_issueA(smbase, 0, hsrc, 0, tid);
                lstm_issueA(smbase, 1, hsrc, 64, tid);
                lstm_issueA(smbase, 2, hsrc, 128, tid);
                #pragma unroll 1
                for (int kt = 0; kt < NKT; ++kt) {
                    if (kt < NKT - 2)      { cp_wait<2>(); }
                    else if (kt == NKT - 2){ cp_wait<1>(); }
                    else                   { cp_wait<0>(); }
                    __syncthreads();
                    if (kt + 3 < NKT)
                        lstm_issueA(smbase, (kt + 3) & 3, hsrc, (kt + 3) * BK, tid);

                    const uint32_t ab = smbase + (uint32_t)(OFF_AS + (kt & 3) * ABUF) * 4u + aoff1;
                    const uint32_t bb = smbase + boff1 + (uint32_t)(kt * 128);
                    #pragma unroll
                    for (int g = 0; g < 4; ++g) {
                        uint32_t af[4], bf[4];
                        ldsm_x4(af, ab + g * 32);
                        ldsm_x4(bf, bb + g * 32);
                        mma_f16(&acc[0][0], af, &bf[0]);
                        mma_f16(&acc[1][0], af, &bf[2]);
                    }
                }
            }

            // epilogue: warp wn == gate index; z (wn==2) -> m; else -> iof smem
            #pragma unroll
            for (int tn = 0; tn < 2; ++tn) {
                #pragma unroll
                for (int jh = 0; jh < 2; ++jh) {
                    const int b = wm * 16 + ar + 8 * jh;
                    const int col0 = tn * 8 + aq * 2;
                    const float s0 = fast_sigmoid(acc[tn][2 * jh + 0] + bhreg[tn][0] + pre2[tn][jh].x);
                    const float s1 = fast_sigmoid(acc[tn][2 * jh + 1] + bhreg[tn][1] + pre2[tn][jh].y);
                    if (wn == 2) {
                        const float m0 = s0 * fast_tanh(c_s[b * IOFP + col0]);
                        const float m1 = s1 * fast_tanh(c_s[b * IOFP + col0 + 1]);
                        *reinterpret_cast<uint32_t*>(
                            g_mh + (size_t)(gRow0 + b) * H + uBase + col0) = pack_h2(m0, m1);
                    } else {
                        const int slot = (wn == 3) ? 2 : wn;
                        iof[slot * IOFSZ + b * IOFP + col0]     = s0;
                        iof[slot * IOFSZ + b * IOFP + col0 + 1] = s1;
                    }
                }
            }
        }
        group_barrier(bar, tgt); tgt += GCTA;

        // ================= Phase 2: u + state update =================
        {
            float2 preu[2];
            if (warp < 8) {
                #pragma unroll
                for (int jh = 0; jh < 2; ++jh) {
                    const int b = wm2 * 16 + ar + 8 * jh;
                    preu[jh] = __ldcg(reinterpret_cast<const float2*>(
                        pre_t + (size_t)(gRow0 + b) * NPRE + 4 * H + uBase + wn2 * 8 + aq * 2));
                }
            }

            float acc2[4] = {};
            if (t > 0) {
                const __half* msrc = g_mh + (size_t)gRow0 * H;
                lstm_issueA(smbase, 0, msrc, 0, tid);
                lstm_issueA(smbase, 1, msrc, 64, tid);
                lstm_issueA(smbase, 2, msrc, 128, tid);
                #pragma unroll 1
                for (int kt = 0; kt < NKT; ++kt) {
                    if (kt < NKT - 2)      { cp_wait<2>(); }
                    else if (kt == NKT - 2){ cp_wait<1>(); }
                    else                   { cp_wait<0>(); }
                    __syncthreads();
                    if (kt + 3 < NKT)
                        lstm_issueA(smbase, (kt + 3) & 3, msrc, (kt + 3) * BK, tid);

                    if (warp < 8) {
                        const uint32_t ab = smbase + (uint32_t)(OFF_AS + (kt & 3) * ABUF) * 4u + aoff2;
                        const uint32_t bb = smbase + boff2 + (uint32_t)(kt * 128);
                        #pragma unroll
                        for (int gp = 0; gp < 2; ++gp) {
                            uint32_t bf[4], af[4];
                            ldsm_x4(bf, bb + gp * 64);
                            ldsm_x4(af, ab + (2 * gp) * 32);
                            mma_f16(acc2, af, &bf[0]);
                            ldsm_x4(af, ab + (2 * gp + 1) * 32);
                            mma_f16(acc2, af, &bf[2]);
                        }
                    }
                }
            }

            if (warp < 8) {
                const int col0 = wn2 * 8 + aq * 2;
                #pragma unroll
                for (int jh = 0; jh < 2; ++jh) {
                    const int b = wm2 * 16 + ar + 8 * jh;
                    const float u0 = fast_tanh(acc2[2 * jh + 0] + bureg[0] + preu[jh].x);
                    const float u1 = fast_tanh(acc2[2 * jh + 1] + bureg[1] + preu[jh].y);
                    const float ig0 = iof[0 * IOFSZ + b * IOFP + col0];
                    const float ig1 = iof[0 * IOFSZ + b * IOFP + col0 + 1];
                    const float og0 = iof[1 * IOFSZ + b * IOFP + col0];
                    const float og1 = iof[1 * IOFSZ + b * IOFP + col0 + 1];
                    const float fg0 = iof[2 * IOFSZ + b * IOFP + col0];
                    const float fg1 = iof[2 * IOFSZ + b * IOFP + col0 + 1];
                    const float cn0 = ig0 * u0 + fg0 * c_s[b * IOFP + col0];
                    const float cn1 = ig1 * u1 + fg1 * c_s[b * IOFP + col0 + 1];
                    c_s[b * IOFP + col0]     = cn0;
                    c_s[b * IOFP + col0 + 1] = cn1;
                    const float hv0 = og0 * fast_tanh(cn0);
                    const float hv1 = og1 * fast_tanh(cn1);
                    *reinterpret_cast<float2*>(
                        out + ((size_t)t * NB + gRow0 + b) * H + uBase + col0) =
                        make_float2(hv0, hv1);
                    *reinterpret_cast<uint32_t*>(
                        g_hh + (size_t)(gRow0 + b) * H + uBase + col0) = pack_h2(hv0, hv1);
                    if (t == SEQ - 1) {
                        float* hn = out + ((size_t)SEQ * NB + gRow0 + b) * H + uBase + col0;
                        float* cn = hn + (size_t)NB * H;
                        *reinterpret_cast<float2*>(hn) = make_float2(hv0, hv1);
                        *reinterpret_cast<float2*>(cn) = make_float2(cn0, cn1);
                    }
                }
            }
        }
        group_barrier(bar, tgt); tgt += GCTA;
    }
}

extern "C" void kernel_launch(void* const* d_in, const int* in_sizes, int n_in,
                              void* d_out, int out_size) {
    (void)in_sizes; (void)n_in; (void)out_size;
    const float* X   = (const float*)d_in[0];
    const float* Wx  = (const float*)d_in[1];
    const float* bx  = (const float*)d_in[2];
    const float* Wh  = (const float*)d_in[3];
    const float* bh  = (const float*)d_in[4];
    const float* Wum = (const float*)d_in[5];
    const float* bum = (const float*)d_in[6];
    float* out = (float*)d_out;

    static_assert(SMEM_WORDS * 4 == 219392, "lstm smem layout");
    cudaFuncSetAttribute(lstm_kernel, cudaFuncAttributeMaxDynamicSharedMemorySize,
                         SMEM_WORDS * 4);
    cudaFuncSetAttribute(pre_kernel, cudaFuncAttributeMaxDynamicSharedMemorySize,
                         P_SMEM * 4);

    const size_t total4 = X4 + W4;
    round_kernel<<<(unsigned)((total4 + 255) / 256), 256>>>(
        (const float4*)X, (const float4*)Wx);
    pre_kernel<<<dim3(NPRE / 128, (SEQ * NB) / 128), 512, P_SMEM * 4>>>(bx);
    lstm_kernel<<<128, 512, SMEM_WORDS * 4>>>(Wh, bh, Wum, bum, out);
}